// round 5
// baseline (speedup 1.0000x reference)
#include <cuda_runtime.h>

// out[n,p,d] = feat[n,p,d] * mean_m(task[n,m,p])
// n=32, m=16, p=1024, d=512

static constexpr int N = 32;
static constexpr int M = 16;
static constexpr int P = 1024;
static constexpr int D = 512;
static constexpr int NP  = N * P;       // 32768 rows
static constexpr int D4  = D / 4;       // 128 float4 per row

static constexpr int TPB = 256;
static constexpr int R   = 16;          // rows per CTA
static constexpr int C4  = R * D4;      // 2048 float4 per CTA
static constexpr int U   = C4 / TPB;    // 8 float4 per thread
static constexpr int GRID = NP / R;     // 2048 CTAs

__global__ void __launch_bounds__(TPB) fused_scale_kernel(
    const float* __restrict__ task,     // [N, M, P]
    const float* __restrict__ feat,     // [N, P, D]
    float* __restrict__ out)            // [N, P, D]
{
    __shared__ float s_mean[32];        // R=16 used; padded

    const int tid   = threadIdx.x;
    const int base4 = blockIdx.x * C4 + tid;   // fits in 32-bit (max ~4.2M)

    const float4* f = reinterpret_cast<const float4*>(feat);
    float4*       o = reinterpret_cast<float4*>(out);

    // ---- Issue all bulk loads FIRST (8 independent LDG.128 per thread).
    //      These remain in flight across the barrier below.
    float4 v[U];
#pragma unroll
    for (int k = 0; k < U; ++k)
        v[k] = f[base4 + k * TPB];

    // ---- Warp 0, lanes 0..R-1: compute the 16 row means (16 independent
    //      strided loads each; overlapped with the feat loads above).
    if (tid < R) {
        const int row = blockIdx.x * R + tid;   // global (n,p) row
        const int n   = row >> 10;              // P = 1024
        const int p   = row & (P - 1);
        const float* t = task + n * (M * P) + p;
        float s = 0.0f;
#pragma unroll
        for (int m = 0; m < M; ++m) s += t[m * P];
        s_mean[tid] = s * (1.0f / (float)M);
    }
    __syncthreads();

    // ---- Multiply + store ----
#pragma unroll
    for (int k = 0; k < U; ++k) {
        const int e    = k * TPB + tid;         // 0..C4-1 within CTA
        const float mn = s_mean[e >> 7];        // local row = e / D4
        v[k].x *= mn; v[k].y *= mn; v[k].z *= mn; v[k].w *= mn;
        o[base4 + k * TPB] = v[k];
    }
}

extern "C" void kernel_launch(void* const* d_in, const int* in_sizes, int n_in,
                              void* d_out, int out_size)
{
    const float* task = (const float*)d_in[0];   // [N, M, P]
    const float* feat = (const float*)d_in[1];   // [N, P, D]
    float* out = (float*)d_out;

    fused_scale_kernel<<<GRID, TPB>>>(task, feat, out);
}

// round 7
// speedup vs baseline: 1.0479x; 1.0479x over previous
#include <cuda_runtime.h>

// out[n,p,d] = feat[n,p,d] * mean_m(task[n,m,p])
// n=32, m=16, p=1024, d=512

static constexpr int N = 32;
static constexpr int M = 16;
static constexpr int P = 1024;
static constexpr int D = 512;
static constexpr int NP = N * P;                 // 32768 rows
static constexpr int D4 = D / 4;                 // 128 float4 per row
static constexpr long long TOTAL4 = (long long)NP * D4;  // 4,194,304 float4

// Scratch for row means (no cudaMalloc allowed).
__device__ float g_mean[NP];

// ---------------------------------------------------------------------------
// Kernel 1: mean over m for each (n,p). 32768 outputs; 2 MB read.
// ---------------------------------------------------------------------------
__global__ void __launch_bounds__(256) mean_kernel(const float* __restrict__ task)
{
    const int np = blockIdx.x * 256 + threadIdx.x;   // 0..NP-1
    const int n  = np >> 10;
    const int p  = np & (P - 1);

    const float* t = task + (size_t)n * M * P + p;
    float s = 0.0f;
#pragma unroll
    for (int m = 0; m < M; ++m) s += t[(size_t)m * P];
    g_mean[np] = s * (1.0f / (float)M);
}

// ---------------------------------------------------------------------------
// Kernel 2: streaming multiply. U=4 independent float4 per thread (the
// proven 18us config). ONE delta vs R2: output stores use __stcs
// (evict-first / streaming) so the write stream does not evict feat from
// L2 -> feat stays L2-resident across graph replays.
// ---------------------------------------------------------------------------
static constexpr int U = 4;
static constexpr int TPB = 256;
static constexpr int GRID2 = (int)(TOTAL4 / (TPB * U));   // 4096 blocks

__global__ void __launch_bounds__(TPB) scale_kernel(
    const float* __restrict__ feat,   // [NP, D]
    float* __restrict__ out)          // [NP, D]
{
    const int base = blockIdx.x * (TPB * U) + threadIdx.x;  // fits 32-bit

    const float4* f = reinterpret_cast<const float4*>(feat);
    float4*       o = reinterpret_cast<float4*>(out);

    int    idx[U];
    float4 v[U];
    float  mn[U];

#pragma unroll
    for (int k = 0; k < U; ++k) {
        idx[k] = base + k * TPB;
        v[k]   = f[idx[k]];                         // independent LDG.128 x4
    }
#pragma unroll
    for (int k = 0; k < U; ++k) {
        mn[k] = __ldg(&g_mean[idx[k] >> 7]);        // row = idx / D4, cached
    }
#pragma unroll
    for (int k = 0; k < U; ++k) {
        v[k].x *= mn[k]; v[k].y *= mn[k];
        v[k].z *= mn[k]; v[k].w *= mn[k];
        __stcs(&o[idx[k]], v[k]);                   // streaming store (.CS)
    }
}

extern "C" void kernel_launch(void* const* d_in, const int* in_sizes, int n_in,
                              void* d_out, int out_size)
{
    const float* task = (const float*)d_in[0];   // [N, M, P]
    const float* feat = (const float*)d_in[1];   // [N, P, D]
    float* out = (float*)d_out;

    mean_kernel<<<NP / 256, 256>>>(task);
    scale_kernel<<<GRID2, TPB>>>(feat, out);
}

// round 8
// speedup vs baseline: 1.1340x; 1.0822x over previous
#include <cuda_runtime.h>

// out[n,p,d] = feat[n,p,d] * mean_m(task[n,m,p])
// n=32, m=16, p=1024, d=512

static constexpr int N = 32;
static constexpr int M = 16;
static constexpr int P = 1024;
static constexpr int D = 512;
static constexpr int NP  = N * P;        // 32768 rows
static constexpr int D4  = D / 4;        // 128 float4 per row

static constexpr int TPB = 256;
static constexpr int R   = 8;            // rows per CTA
static constexpr int C4  = R * D4;       // 1024 float4 per CTA
static constexpr int U   = 4;            // float4 per thread (C4 / TPB)
static constexpr int GRID = NP / R;      // 4096 CTAs (same shape as R2 winner)

// Warp w accesses elements e = (w*32 + lane) + 256*k, local row = e>>7 =
// (w>>2) + 2k. So each warp needs exactly 4 row means: (w>>2) + 2k, k=0..3.
// Computed warp-locally: lanes 0..15 load the 16 m-values, SHFL-reduce.
// No __syncthreads, no shared memory -> no barrier serialization.

__global__ void __launch_bounds__(TPB) fused_kernel(
    const float* __restrict__ task,     // [N, M, P]
    const float* __restrict__ feat,     // [N, P, D]
    float* __restrict__ out)            // [N, P, D]
{
    const int tid   = threadIdx.x;
    const int lane  = tid & 31;
    const int w     = tid >> 5;
    const int base4 = blockIdx.x * C4 + tid;     // fits 32-bit

    const float4* f = reinterpret_cast<const float4*>(feat);
    float4*       o = reinterpret_cast<float4*>(out);

    // ---- 1) Issue the bulk feat loads first (4 independent LDG.128) ----
    float4 v[U];
#pragma unroll
    for (int k = 0; k < U; ++k)
        v[k] = f[base4 + k * TPB];

    // ---- 2) Warp-local row means (overlap with feat loads in flight) ----
    float mean_r[U];
#pragma unroll
    for (int r = 0; r < U; ++r) {
        const int lrow = (w >> 2) + 2 * r;           // local row 0..7
        const int grow = blockIdx.x * R + lrow;      // global (n,p) row
        const int n    = grow >> 10;                 // P = 1024
        const int p    = grow & (P - 1);
        float x = 0.0f;
        if (lane < M)
            x = task[n * (M * P) + lane * P + p];    // lane = m index
        // reduce 16 lanes, then mirror into upper half (which holds 0)
        x += __shfl_xor_sync(0xFFFFFFFFu, x, 8);
        x += __shfl_xor_sync(0xFFFFFFFFu, x, 4);
        x += __shfl_xor_sync(0xFFFFFFFFu, x, 2);
        x += __shfl_xor_sync(0xFFFFFFFFu, x, 1);
        x += __shfl_xor_sync(0xFFFFFFFFu, x, 16);
        mean_r[r] = x * (1.0f / (float)M);
    }

    // ---- 3) Multiply + store (access k uses row (w>>2)+2k == mean_r[k]) ----
#pragma unroll
    for (int k = 0; k < U; ++k) {
        const float mn = mean_r[k];
        v[k].x *= mn; v[k].y *= mn; v[k].z *= mn; v[k].w *= mn;
        o[base4 + k * TPB] = v[k];
    }
}

extern "C" void kernel_launch(void* const* d_in, const int* in_sizes, int n_in,
                              void* d_out, int out_size)
{
    const float* task = (const float*)d_in[0];   // [N, M, P]
    const float* feat = (const float*)d_in[1];   // [N, P, D]
    float* out = (float*)d_out;

    fused_kernel<<<GRID, TPB>>>(task, feat, out);
}

// round 10
// speedup vs baseline: 1.2458x; 1.0986x over previous
#include <cuda_runtime.h>

// out[n,p,d] = feat[n,p,d] * mean_m(task[n,m,p])
// n=32, m=16, p=1024, d=512

static constexpr int N = 32;
static constexpr int M = 16;
static constexpr int P = 1024;
static constexpr int D = 512;
static constexpr int NP  = N * P;        // 32768 rows
static constexpr int D4  = D / 4;        // 128 float4 per row

static constexpr int TPB = 256;
static constexpr int R   = 8;            // rows per CTA == warps per CTA
static constexpr int C4  = R * D4;       // 1024 float4 per CTA
static constexpr int U   = 4;            // float4 per thread
static constexpr int GRID = NP / R;      // 4096 CTAs

__global__ void __launch_bounds__(TPB) fused_kernel(
    const float* __restrict__ task,     // [N, M, P]
    const float* __restrict__ feat,     // [N, P, D]
    float* __restrict__ out)            // [N, P, D]
{
    __shared__ float s_mean[R];

    const int tid   = threadIdx.x;
    const int lane  = tid & 31;
    const int w     = tid >> 5;                  // 0..7, also the local row
    const int base4 = blockIdx.x * C4 + tid;     // fits 32-bit

    const float4* f = reinterpret_cast<const float4*>(feat);
    float4*       o = reinterpret_cast<float4*>(out);

    // ---- 1) Issue the bulk feat loads first (4 independent LDG.128).
    //         They remain in flight across the barrier below.
    float4 v[U];
#pragma unroll
    for (int k = 0; k < U; ++k)
        v[k] = f[base4 + k * TPB];

    // ---- 2) Each warp computes ONE row mean (row == warp id).
    //         Lanes 0..15 load the 16 m-values; 4-level SHFL reduce.
    {
        const int grow = blockIdx.x * R + w;     // global (n,p) row
        const int n    = grow >> 10;             // P = 1024
        const int p    = grow & (P - 1);
        float x = 0.0f;
        if (lane < M)
            x = task[n * (M * P) + lane * P + p];   // lane = m index
        x += __shfl_xor_sync(0xFFFFFFFFu, x, 8);
        x += __shfl_xor_sync(0xFFFFFFFFu, x, 4);
        x += __shfl_xor_sync(0xFFFFFFFFu, x, 2);
        x += __shfl_xor_sync(0xFFFFFFFFu, x, 1);
        if (lane == 0)
            s_mean[w] = x * (1.0f / (float)M);
    }
    __syncthreads();

    // ---- 3) Multiply + store. Access k touches local row (w>>2) + 2k;
    //         LDS is warp-uniform -> broadcast, conflict-free.
#pragma unroll
    for (int k = 0; k < U; ++k) {
        const float mn = s_mean[(w >> 2) + 2 * k];
        v[k].x *= mn; v[k].y *= mn; v[k].z *= mn; v[k].w *= mn;
        o[base4 + k * TPB] = v[k];
    }
}

extern "C" void kernel_launch(void* const* d_in, const int* in_sizes, int n_in,
                              void* d_out, int out_size)
{
    const float* task = (const float*)d_in[0];   // [N, M, P]
    const float* feat = (const float*)d_in[1];   // [N, P, D]
    float* out = (float*)d_out;

    fused_kernel<<<GRID, TPB>>>(task, feat, out);
}